// round 11
// baseline (speedup 1.0000x reference)
#include <cuda_runtime.h>

// diag(ics_mask - params * r_mask) for N=12288 -> [N, N] fp32 output.
// Pure store-bandwidth kernel (604 MB out). R10 profile: dram=83%, occ=45.9%
// with 150-cycle CTA lifetimes -> CTA-launch-rate starvation. Fix: 8 float4
// stores per thread (128 B/thread), 18432 blocks, each store warp-coalesced
// via k*TPB striding. Diagonal folded in via constant-divisor magic multiply.

static constexpr int N = 12288;
static constexpr int NP1 = N + 1;                       // 12289
static constexpr unsigned int TOTAL = (unsigned int)N * (unsigned int)N;  // 150,994,944
static constexpr unsigned int NVEC = TOTAL / 4;         // 37,748,736 float4s
static constexpr int TPB = 256;
static constexpr int ITEMS = 8;                         // float4s per thread
static constexpr unsigned int VPB = (unsigned int)TPB * ITEMS;   // 2048 float4s / block
static constexpr unsigned int NBLK = NVEC / VPB;        // 18,432 (exact)

__global__ __launch_bounds__(TPB) void diag_fill_kernel(
    const float* __restrict__ params,
    const int* __restrict__ r_mask,
    const int* __restrict__ ics_mask,
    float4* __restrict__ out)
{
    // Block covers a contiguous 2048-float4 (32 KB) region; item k of each
    // thread is at base + k*TPB so every STG.128 is fully warp-coalesced.
    unsigned int base = blockIdx.x * VPB + threadIdx.x;

#pragma unroll
    for (int k = 0; k < ITEMS; k++) {
        unsigned int v = base + (unsigned int)k * (unsigned int)TPB;
        unsigned int e = v * 4u;                        // element range [e, e+4)

        float4 z = make_float4(0.0f, 0.0f, 0.0f, 0.0f);

        // Unique diagonal index i with i*(N+1) in [e, e+4), if any:
        // i = ceil(e / (N+1)); constant divisor -> IMAD magic multiply.
        unsigned int i = (e + (unsigned int)N) / (unsigned int)NP1;
        if (i < (unsigned int)N) {
            unsigned int p = i * (unsigned int)NP1;
            if (p < e + 4u) {
                float dv = (float)ics_mask[i] - params[i] * (float)r_mask[i];
                ((float*)&z)[p - e] = dv;
            }
        }

        __stcs(&out[v], z);   // evict-first streaming store
    }
}

extern "C" void kernel_launch(void* const* d_in, const int* in_sizes, int n_in,
                              void* d_out, int out_size)
{
    const float* params   = (const float*)d_in[0];
    const int*   r_mask   = (const int*)d_in[1];
    const int*   ics_mask = (const int*)d_in[2];
    float4*      out      = (float4*)d_out;

    diag_fill_kernel<<<NBLK, TPB>>>(params, r_mask, ics_mask, out);
}